// round 9
// baseline (speedup 1.0000x reference)
#include <cuda_runtime.h>
#include <cuda_bf16.h>
#include <cstdint>

// MHC fused: persistent work-stealing at 2 CTAs/SM (512 thr each, 64 regs).
// The two resident CTAs interleave naturally: while one sits in its reduce
// barrier / store burst, the other's front-batched LDG.128s keep DRAM busy.
// Work-stealing via self-resetting global ticket (graph-replay safe).
// Per-row body is the R5 64-reg layout: params in smem, va[32] live across
// the barrier, P/hpost pulled from smem post-barrier.

#define NS        4
#define CDIM      4096
#define C4        (CDIM / 4)
#define THREADS   512
#define NWARPS    (THREADS / 32)
#define EPSF      1e-6f
#define SINKITERS 3
#define ROW_BYTES (NS * CDIM * 4)   // 65536 = 512 threads * 128B

__device__ int g_ticket = 0;
__device__ int g_done   = 0;

__device__ __forceinline__ void pf_l2(const void* p) {
    asm volatile("prefetch.global.L2 [%0];" :: "l"(p));
}

__global__ __launch_bounds__(THREADS, 2)
void mhc_ws3_kernel(const float* __restrict__ x,
                    const float* __restrict__ w,
                    const float* __restrict__ Hpre,
                    const float* __restrict__ Hpost,
                    const float* __restrict__ Hres,
                    float* __restrict__ out, int B)
{
    __shared__ float ps[24];                 // hpre[4], hpost[4], P[16]
    __shared__ float wsum[2][NWARPS];
    __shared__ int   nrow[2];

    const int tid = threadIdx.x, lane = tid & 31, wid = tid >> 5;

    // ---- Warp 0: tiny params once per CTA -> smem ----
    if (wid == 0) {
        float hpre[NS], hpost[NS], P[NS][NS];
        #pragma unroll
        for (int i = 0; i < NS; i++) {
            hpre[i]  = 1.0f / (1.0f + expf(-Hpre[i]));
            hpost[i] = 2.0f / (1.0f + expf(-Hpost[i]));
        }
        #pragma unroll
        for (int i = 0; i < NS; i++)
            #pragma unroll
            for (int j = 0; j < NS; j++)
                P[i][j] = expf(Hres[i * NS + j]);
        #pragma unroll
        for (int it = 0; it < SINKITERS; it++) {
            #pragma unroll
            for (int i = 0; i < NS; i++) {
                float ri = 1.0f / (P[i][0] + P[i][1] + P[i][2] + P[i][3] + EPSF);
                #pragma unroll
                for (int j = 0; j < NS; j++) P[i][j] *= ri;
            }
            #pragma unroll
            for (int j = 0; j < NS; j++) {
                float ci = 1.0f / (P[0][j] + P[1][j] + P[2][j] + P[3][j] + EPSF);
                #pragma unroll
                for (int i = 0; i < NS; i++) P[i][j] *= ci;
            }
        }
        if (lane == 0) {
            #pragma unroll
            for (int i = 0; i < NS; i++) { ps[i] = hpre[i]; ps[4 + i] = hpost[i]; }
            #pragma unroll
            for (int i = 0; i < NS; i++)
                #pragma unroll
                for (int j = 0; j < NS; j++)
                    ps[8 + i * NS + j] = P[i][j];
        }
    }

    // ---- First two tickets ----
    if (tid == 0) {
        nrow[0] = atomicAdd(&g_ticket, 1);
        nrow[1] = atomicAdd(&g_ticket, 1);
    }
    __syncthreads();

    // rmsnorm weight in registers (8 regs; rest of params stay in smem)
    const float4 wv0 = __ldg(reinterpret_cast<const float4*>(w) + tid);
    const float4 wv1 = __ldg(reinterpret_cast<const float4*>(w) + tid + THREADS);

    const char* __restrict__ xb = reinterpret_cast<const char*>(x);
    int cur = nrow[0], nxt = nrow[1];

    // Warm L2 with the first row
    if (cur < B) pf_l2(xb + (size_t)cur * ROW_BYTES + tid * 128);

    int k = 0;
    while (cur < B) {
        // ---- Prefetch next row into L2 (1 line/thread, 0 extra regs) ----
        if (nxt < B)
            pf_l2(xb + (size_t)nxt * ROW_BYTES + tid * 128);

        // ---- Front-batched loads of current row, evict-first ----
        const float4* __restrict__ xr =
            reinterpret_cast<const float4*>(xb + (size_t)cur * ROW_BYTES);
        float4 v4[NS][2];
        #pragma unroll
        for (int n = 0; n < NS; n++) {
            v4[n][0] = __ldcs(&xr[n * C4 + tid]);
            v4[n][1] = __ldcs(&xr[n * C4 + tid + THREADS]);
        }

        // ---- Next ticket (published by this iteration's barrier) ----
        if (tid == 0) nrow[k & 1] = atomicAdd(&g_ticket, 1);

        // ---- Unpack ----
        float va[NS][8];
        #pragma unroll
        for (int n = 0; n < NS; n++) {
            va[n][0] = v4[n][0].x; va[n][1] = v4[n][0].y;
            va[n][2] = v4[n][0].z; va[n][3] = v4[n][0].w;
            va[n][4] = v4[n][1].x; va[n][5] = v4[n][1].y;
            va[n][6] = v4[n][1].z; va[n][7] = v4[n][1].w;
        }

        // ---- agg (gates from smem) + bf16 round-trip + sum of squares ----
        const float h0 = ps[0], h1 = ps[1], h2 = ps[2], h3 = ps[3];
        float agg[8];
        float ss = 0.0f;
        #pragma unroll
        for (int e = 0; e < 8; e++) {
            float a = h0 * va[0][e] + h1 * va[1][e]
                    + h2 * va[2][e] + h3 * va[3][e];
            a = __bfloat162float(__float2bfloat16_rn(a));
            agg[e] = a;
            ss += a * a;
        }

        // ---- Block reduce (single barrier, parity slots) ----
        #pragma unroll
        for (int o = 16; o > 0; o >>= 1)
            ss += __shfl_xor_sync(0xffffffffu, ss, o);
        if (lane == 0) wsum[k & 1][wid] = ss;
        __syncthreads();
        float tot = 0.0f;
        #pragma unroll
        for (int i = 0; i < NWARPS; i++) tot += wsum[k & 1][i];
        const float rinv = rsqrtf(tot * (1.0f / CDIM) + EPSF);
        const int nn = nrow[k & 1];

        // ---- t = agg_bf * w ----
        float t[8];
        t[0] = agg[0] * wv0.x; t[1] = agg[1] * wv0.y;
        t[2] = agg[2] * wv0.z; t[3] = agg[3] * wv0.w;
        t[4] = agg[4] * wv1.x; t[5] = agg[5] * wv1.y;
        t[6] = agg[6] * wv1.z; t[7] = agg[7] * wv1.w;

        // ---- Mix (P, hpost from smem post-barrier) + streaming stores ----
        float4* __restrict__ orow =
            reinterpret_cast<float4*>(out) + (size_t)cur * (NS * C4);
        #pragma unroll
        for (int i = 0; i < NS; i++) {
            const float p0 = ps[8 + i * NS + 0], p1 = ps[8 + i * NS + 1];
            const float p2 = ps[8 + i * NS + 2], p3 = ps[8 + i * NS + 3];
            const float h  = ps[4 + i] * rinv;
            float o[8];
            #pragma unroll
            for (int e = 0; e < 8; e++) {
                o[e] = p0 * va[0][e] + p1 * va[1][e]
                     + p2 * va[2][e] + p3 * va[3][e]
                     + h * t[e];
            }
            __stcs(&orow[i * C4 + tid],
                   make_float4(o[0], o[1], o[2], o[3]));
            __stcs(&orow[i * C4 + tid + THREADS],
                   make_float4(o[4], o[5], o[6], o[7]));
        }

        cur = nxt; nxt = nn; k++;
    }

    // ---- Self-reset for graph replay: last CTA zeroes the counters ----
    if (tid == 0) {
        int d = atomicAdd(&g_done, 1);
        if (d == (int)gridDim.x - 1) {
            g_ticket = 0;
            g_done   = 0;
        }
    }
}

extern "C" void kernel_launch(void* const* d_in, const int* in_sizes, int n_in,
                              void* d_out, int out_size)
{
    const float* x      = (const float*)d_in[0];
    const float* w      = (const float*)d_in[1];
    const float* H_pre  = (const float*)d_in[2];
    const float* H_post = (const float*)d_in[3];
    const float* H_res  = (const float*)d_in[4];
    float* out          = (float*)d_out;

    const int B = in_sizes[0] / (NS * CDIM);

    int dev = 0, nsm = 148;
    cudaGetDevice(&dev);
    cudaDeviceGetAttribute(&nsm, cudaDevAttrMultiProcessorCount, dev);

    mhc_ws3_kernel<<<2 * nsm, THREADS>>>(x, w, H_pre, H_post, H_res, out, B);
}

// round 10
// speedup vs baseline: 1.0051x; 1.0051x over previous
#include <cuda_runtime.h>
#include <cuda_bf16.h>
#include <cstdint>

// MHC fused: persistent work-stealing over ROW PAIRS (rows 2p, 2p+1).
// grid = #SMs, 1 CTA/SM, 512 threads, ~110 regs. Per iteration:
//  - prefetch next pair (128KB contiguous) into L2
//  - 16 front-batched LDG.128 (contiguous 128KB read burst)
//  - ONE barrier reduces both rows' RMS sums
//  - 128KB contiguous streaming write burst
// Ticket counts pairs; self-resets for graph replay. B assumed even (8192).

#define NS        4
#define CDIM      4096
#define C4        (CDIM / 4)
#define THREADS   512
#define NWARPS    (THREADS / 32)
#define EPSF      1e-6f
#define SINKITERS 3
#define ROW_BYTES  (NS * CDIM * 4)      // 65536
#define PAIR_BYTES (2 * ROW_BYTES)      // 131072

__device__ int g_ticket = 0;
__device__ int g_done   = 0;

__device__ __forceinline__ void pf_l2(const void* p) {
    asm volatile("prefetch.global.L2 [%0];" :: "l"(p));
}

__global__ __launch_bounds__(THREADS, 1)
void mhc_pair_kernel(const float* __restrict__ x,
                     const float* __restrict__ w,
                     const float* __restrict__ Hpre,
                     const float* __restrict__ Hpost,
                     const float* __restrict__ Hres,
                     float* __restrict__ out, int B)
{
    __shared__ float ps[24];                 // hpre[4], hpost[4], P[16]
    __shared__ float wsA[2][NWARPS], wsB[2][NWARPS];
    __shared__ int   npair[2];

    const int tid = threadIdx.x, lane = tid & 31, wid = tid >> 5;
    const int NP = B >> 1;                   // number of pairs

    // ---- Warp 0: tiny params once -> smem ----
    if (wid == 0) {
        float hpre[NS], hpost[NS], P[NS][NS];
        #pragma unroll
        for (int i = 0; i < NS; i++) {
            hpre[i]  = 1.0f / (1.0f + expf(-Hpre[i]));
            hpost[i] = 2.0f / (1.0f + expf(-Hpost[i]));
        }
        #pragma unroll
        for (int i = 0; i < NS; i++)
            #pragma unroll
            for (int j = 0; j < NS; j++)
                P[i][j] = expf(Hres[i * NS + j]);
        #pragma unroll
        for (int it = 0; it < SINKITERS; it++) {
            #pragma unroll
            for (int i = 0; i < NS; i++) {
                float ri = 1.0f / (P[i][0] + P[i][1] + P[i][2] + P[i][3] + EPSF);
                #pragma unroll
                for (int j = 0; j < NS; j++) P[i][j] *= ri;
            }
            #pragma unroll
            for (int j = 0; j < NS; j++) {
                float ci = 1.0f / (P[0][j] + P[1][j] + P[2][j] + P[3][j] + EPSF);
                #pragma unroll
                for (int i = 0; i < NS; i++) P[i][j] *= ci;
            }
        }
        if (lane == 0) {
            #pragma unroll
            for (int i = 0; i < NS; i++) { ps[i] = hpre[i]; ps[4 + i] = hpost[i]; }
            #pragma unroll
            for (int i = 0; i < NS; i++)
                #pragma unroll
                for (int j = 0; j < NS; j++)
                    ps[8 + i * NS + j] = P[i][j];
        }
    }

    // ---- First two pair tickets ----
    if (tid == 0) {
        npair[0] = atomicAdd(&g_ticket, 1);
        npair[1] = atomicAdd(&g_ticket, 1);
    }
    __syncthreads();

    const float4 wv0 = __ldg(reinterpret_cast<const float4*>(w) + tid);
    const float4 wv1 = __ldg(reinterpret_cast<const float4*>(w) + tid + THREADS);

    const char* __restrict__ xb = reinterpret_cast<const char*>(x);
    int cur = npair[0], nxt = npair[1];

    // Warm L2 with the first pair (2 lines/thread = 128KB)
    if (cur < NP) {
        const char* g = xb + (size_t)cur * PAIR_BYTES;
        pf_l2(g + tid * 128);
        pf_l2(g + ROW_BYTES + tid * 128);
    }

    int k = 0;
    while (cur < NP) {
        // ---- Prefetch next pair into L2 ----
        if (nxt < NP) {
            const char* g = xb + (size_t)nxt * PAIR_BYTES;
            pf_l2(g + tid * 128);
            pf_l2(g + ROW_BYTES + tid * 128);
        }

        // ---- Front-batched loads: 16x LDG.128, contiguous 128KB ----
        const float4* __restrict__ xra =
            reinterpret_cast<const float4*>(xb + (size_t)cur * PAIR_BYTES);
        const float4* __restrict__ xrb = xra + NS * C4;
        float4 a4[NS][2], b4[NS][2];
        #pragma unroll
        for (int n = 0; n < NS; n++) {
            a4[n][0] = __ldcs(&xra[n * C4 + tid]);
            a4[n][1] = __ldcs(&xra[n * C4 + tid + THREADS]);
        }
        #pragma unroll
        for (int n = 0; n < NS; n++) {
            b4[n][0] = __ldcs(&xrb[n * C4 + tid]);
            b4[n][1] = __ldcs(&xrb[n * C4 + tid + THREADS]);
        }

        // ---- Next pair ticket (published by this iteration's barrier) ----
        if (tid == 0) npair[k & 1] = atomicAdd(&g_ticket, 1);

        // ---- agg for both rows + bf16 round-trip + sums of squares ----
        const float h0 = ps[0], h1 = ps[1], h2 = ps[2], h3 = ps[3];
        float aggA[8], aggB[8];
        float ssA = 0.0f, ssB = 0.0f;
        #pragma unroll
        for (int e = 0; e < 8; e++) {
            const int s = e >> 2, c = e & 3;
            float xa0 = (&a4[0][s].x)[c], xa1 = (&a4[1][s].x)[c];
            float xa2 = (&a4[2][s].x)[c], xa3 = (&a4[3][s].x)[c];
            float aA = h0 * xa0 + h1 * xa1 + h2 * xa2 + h3 * xa3;
            aA = __bfloat162float(__float2bfloat16_rn(aA));
            aggA[e] = aA; ssA += aA * aA;

            float xb0 = (&b4[0][s].x)[c], xb1 = (&b4[1][s].x)[c];
            float xb2 = (&b4[2][s].x)[c], xb3 = (&b4[3][s].x)[c];
            float aB = h0 * xb0 + h1 * xb1 + h2 * xb2 + h3 * xb3;
            aB = __bfloat162float(__float2bfloat16_rn(aB));
            aggB[e] = aB; ssB += aB * aB;
        }

        // ---- Single barrier reduces BOTH rows ----
        #pragma unroll
        for (int o = 16; o > 0; o >>= 1) {
            ssA += __shfl_xor_sync(0xffffffffu, ssA, o);
            ssB += __shfl_xor_sync(0xffffffffu, ssB, o);
        }
        if (lane == 0) { wsA[k & 1][wid] = ssA; wsB[k & 1][wid] = ssB; }
        __syncthreads();
        float totA = 0.0f, totB = 0.0f;
        #pragma unroll
        for (int i = 0; i < NWARPS; i++) {
            totA += wsA[k & 1][i];
            totB += wsB[k & 1][i];
        }
        const float rinvA = rsqrtf(totA * (1.0f / CDIM) + EPSF);
        const float rinvB = rsqrtf(totB * (1.0f / CDIM) + EPSF);
        const int nn = npair[k & 1];

        // ---- t = agg_bf * w for both rows ----
        const float wa[8] = {wv0.x, wv0.y, wv0.z, wv0.w,
                             wv1.x, wv1.y, wv1.z, wv1.w};
        float tA[8], tB[8];
        #pragma unroll
        for (int e = 0; e < 8; e++) { tA[e] = aggA[e] * wa[e]; tB[e] = aggB[e] * wa[e]; }

        // ---- Mix + contiguous 128KB streaming write burst ----
        float4* __restrict__ oa =
            reinterpret_cast<float4*>(out) + (size_t)cur * (2 * NS * C4);
        float4* __restrict__ ob = oa + NS * C4;
        #pragma unroll
        for (int i = 0; i < NS; i++) {
            const float p0 = ps[8 + i * NS + 0], p1 = ps[8 + i * NS + 1];
            const float p2 = ps[8 + i * NS + 2], p3 = ps[8 + i * NS + 3];
            const float hA = ps[4 + i] * rinvA;
            float o[8];
            #pragma unroll
            for (int e = 0; e < 8; e++) {
                const int s = e >> 2, c = e & 3;
                o[e] = p0 * (&a4[0][s].x)[c] + p1 * (&a4[1][s].x)[c]
                     + p2 * (&a4[2][s].x)[c] + p3 * (&a4[3][s].x)[c]
                     + hA * tA[e];
            }
            __stcs(&oa[i * C4 + tid],           make_float4(o[0], o[1], o[2], o[3]));
            __stcs(&oa[i * C4 + tid + THREADS], make_float4(o[4], o[5], o[6], o[7]));
        }
        #pragma unroll
        for (int i = 0; i < NS; i++) {
            const float p0 = ps[8 + i * NS + 0], p1 = ps[8 + i * NS + 1];
            const float p2 = ps[8 + i * NS + 2], p3 = ps[8 + i * NS + 3];
            const float hB = ps[4 + i] * rinvB;
            float o[8];
            #pragma unroll
            for (int e = 0; e < 8; e++) {
                const int s = e >> 2, c = e & 3;
                o[e] = p0 * (&b4[0][s].x)[c] + p1 * (&b4[1][s].x)[c]
                     + p2 * (&b4[2][s].x)[c] + p3 * (&b4[3][s].x)[c]
                     + hB * tB[e];
            }
            __stcs(&ob[i * C4 + tid],           make_float4(o[0], o[1], o[2], o[3]));
            __stcs(&ob[i * C4 + tid + THREADS], make_float4(o[4], o[5], o[6], o[7]));
        }

        cur = nxt; nxt = nn; k++;
    }

    // ---- Self-reset for graph replay ----
    if (tid == 0) {
        int d = atomicAdd(&g_done, 1);
        if (d == (int)gridDim.x - 1) {
            g_ticket = 0;
            g_done   = 0;
        }
    }
}

extern "C" void kernel_launch(void* const* d_in, const int* in_sizes, int n_in,
                              void* d_out, int out_size)
{
    const float* x      = (const float*)d_in[0];
    const float* w      = (const float*)d_in[1];
    const float* H_pre  = (const float*)d_in[2];
    const float* H_post = (const float*)d_in[3];
    const float* H_res  = (const float*)d_in[4];
    float* out          = (float*)d_out;

    const int B = in_sizes[0] / (NS * CDIM);

    int dev = 0, nsm = 148;
    cudaGetDevice(&dev);
    cudaDeviceGetAttribute(&nsm, cudaDevAttrMultiProcessorCount, dev);

    mhc_pair_kernel<<<nsm, THREADS>>>(x, w, H_pre, H_post, H_res, out, B);
}